// round 7
// baseline (speedup 1.0000x reference)
#include <cuda_runtime.h>
#include <cuda_bf16.h>
#include <math.h>
#include <stdint.h>

#define VN    8192
#define NCOL  64
#define KA    72            // smem row stride in bf16 (144B, LDSM conflict-free)

// smem plane byte offsets within one buffer
#define AHI_OFF 0
#define ALO_OFF 18432       // 128*72*2
#define BHI_OFF 36864
#define BLO_OFF 46080       // +64*72*2
#define BUFSZ   55296
#define DSMEM_GEMM (2*BUFSZ)
#define DSMEM_H1   BUFSZ

// ---------------- device scratch ---------------------------------------------
__device__ __nv_bfloat16 g_adjh[(size_t)VN * VN];   // blended adj, bf16 hi
__device__ __nv_bfloat16 g_adjl[(size_t)VN * VN];   // bf16 lo residual
__device__ float g_rowsum[VN];
__device__ float g_rspart[4][VN];
__device__ float g_part[4][(size_t)VN * NCOL];
__device__ float g_X[(size_t)VN * NCOL];            // hop output [v][col]
__device__ __nv_bfloat16 g_XTh[(size_t)NCOL * VN];  // transposed, split
__device__ __nv_bfloat16 g_XTl[(size_t)NCOL * VN];
__device__ float g_w4[4];
__device__ float g_s1[256 * 128];
__device__ float g_s2[256 * 128];
__device__ float g_mu[128];
__device__ float g_rstd[128];

// ---------------- helpers ------------------------------------------------------
__device__ __forceinline__ uint32_t smem_u32(const void* p) {
    uint32_t a;
    asm("{ .reg .u64 t; cvta.to.shared.u64 t, %1; cvt.u32.u64 %0, t; }" : "=r"(a) : "l"(p));
    return a;
}
__device__ __forceinline__ void bsplit(float x, float y, uint32_t& hi, uint32_t& lo) {
    __nv_bfloat162 h = __floats2bfloat162_rn(x, y);
    float hx = __bfloat162float(h.x), hy = __bfloat162float(h.y);
    __nv_bfloat162 l = __floats2bfloat162_rn(x - hx, y - hy);
    hi = *reinterpret_cast<uint32_t*>(&h);
    lo = *reinterpret_cast<uint32_t*>(&l);
}
__device__ __forceinline__ void mma_bf16(float* c,
    uint32_t a0, uint32_t a1, uint32_t a2, uint32_t a3, uint32_t b0, uint32_t b1) {
    asm volatile(
        "mma.sync.aligned.m16n8k16.row.col.f32.bf16.bf16.f32 "
        "{%0,%1,%2,%3}, {%4,%5,%6,%7}, {%8,%9}, {%0,%1,%2,%3};"
        : "+f"(c[0]), "+f"(c[1]), "+f"(c[2]), "+f"(c[3])
        : "r"(a0), "r"(a1), "r"(a2), "r"(a3), "r"(b0), "r"(b1));
}
__device__ __forceinline__ void ldsm4(uint32_t addr, uint32_t* r) {
    asm volatile("ldmatrix.sync.aligned.m8n8.x4.shared.b16 {%0,%1,%2,%3}, [%4];"
        : "=r"(r[0]), "=r"(r[1]), "=r"(r[2]), "=r"(r[3]) : "r"(addr));
}
__device__ __forceinline__ void cpa16(uint32_t dst, const void* src) {
    asm volatile("cp.async.cg.shared.global [%0], [%1], 16;" :: "r"(dst), "l"(src) : "memory");
}
#define CP_COMMIT() asm volatile("cp.async.commit_group;" ::: "memory")

// shared microkernel: one 128x64x64 k-tile, 3-term bf16 split.
// aoff: per-thread ldmatrix byte offset into A planes; boff[g]: into B planes.
__device__ __forceinline__ void mma_tile(uint32_t base, float acc[8][4],
                                         uint32_t aoff, const uint32_t* boff) {
#pragma unroll
    for (int ks = 0; ks < 4; ++ks) {
        const uint32_t kb = ks * 32;
        uint32_t ah[4], al[4];
        ldsm4(base + AHI_OFF + aoff + kb, ah);
        ldsm4(base + ALO_OFF + aoff + kb, al);
#pragma unroll
        for (int g = 0; g < 4; ++g) {
            uint32_t bh[4], bl[4];
            ldsm4(base + BHI_OFF + boff[g] + kb, bh);
            ldsm4(base + BLO_OFF + boff[g] + kb, bl);
            mma_bf16(acc[2*g],   ah[0],ah[1],ah[2],ah[3], bh[0],bh[1]);
            mma_bf16(acc[2*g],   ah[0],ah[1],ah[2],ah[3], bl[0],bl[1]);
            mma_bf16(acc[2*g],   al[0],al[1],al[2],al[3], bh[0],bh[1]);
            mma_bf16(acc[2*g+1], ah[0],ah[1],ah[2],ah[3], bh[2],bh[3]);
            mma_bf16(acc[2*g+1], ah[0],ah[1],ah[2],ah[3], bl[2],bl[3]);
            mma_bf16(acc[2*g+1], al[0],al[1],al[2],al[3], bh[2],bh[3]);
        }
    }
}

__device__ __forceinline__ void frag_offsets(int lane, int wid, uint32_t& aoff, uint32_t* boff) {
    const int rr = lane & 7, sel = lane >> 3;
    aoff = ((wid * 16 + (sel & 1) * 8 + rr) * KA + (sel >> 1) * 8) * 2;
#pragma unroll
    for (int g = 0; g < 4; ++g)
        boff[g] = ((g * 16 + (sel >> 1) * 8 + rr) * KA + (sel & 1) * 8) * 2;
}

// epilogue: write per-warp accumulators to split-K partial buffer
__device__ __forceinline__ void write_partials(float acc[8][4], int s, int vbase,
                                               int wid, int lane) {
    float* dst = g_part[s] + (size_t)(vbase + wid * 16) * NCOL;
    const int gr = lane >> 2, cq = (lane & 3) * 2;
#pragma unroll
    for (int nb = 0; nb < 8; ++nb) {
        const int col = nb * 8 + cq;
        *(float2*)(dst + (size_t)gr * NCOL + col)       = make_float2(acc[nb][0], acc[nb][1]);
        *(float2*)(dst + (size_t)(gr + 8) * NCOL + col) = make_float2(acc[nb][2], acc[nb][3]);
    }
}

// ---------------- alpha softmax ----------------------------------------------
__global__ void k_alpha(const float* __restrict__ af, const float* __restrict__ as) {
    float e0 = expf(af[0]), e1 = expf(af[1]);
    g_w4[0] = e0 / (e0 + e1); g_w4[1] = e1 / (e0 + e1);
    float f0 = expf(as[0]), f1 = expf(as[1]);
    g_w4[2] = f0 / (f0 + f1); g_w4[3] = f1 / (f0 + f1);
}

// ---------------- fused hop1: blend + split-store adj + rowsum + GEMM --------
// grid (64, 4): 128-row M tiles x split-K quarters (KSPAN=2048, 32 tiles).
__global__ __launch_bounds__(256, 2) void k_hop1(
    const float* __restrict__ adjf, const float* __restrict__ adjs,
    const float* __restrict__ adjm, const float* __restrict__ data)
{
    extern __shared__ __align__(16) char smem[];
    const uint32_t base = smem_u32(smem);
    const int tid = threadIdx.x, lane = tid & 31, wid = tid >> 5;
    const int vbase = blockIdx.x * 128;
    const int s = blockIdx.y;
    const int kbase = s * 2048;
    const float w0 = g_w4[0], w1 = g_w4[1], w2 = g_w4[2], w3 = g_w4[3];

    uint32_t aoff, boff[4];
    frag_offsets(lane, wid, aoff, boff);

    float acc[8][4];
#pragma unroll
    for (int i = 0; i < 8; ++i)
#pragma unroll
        for (int j = 0; j < 4; ++j) acc[i][j] = 0.f;
    float rsp[8] = {0.f,0.f,0.f,0.f,0.f,0.f,0.f,0.f};

    const int arow = tid >> 4;
    const int ac4 = (tid & 15) << 2;
    const float* __restrict__ pf1 = adjf + (size_t)VN * VN;
    const float* __restrict__ ps1 = adjs + (size_t)VN * VN;

    for (int t = 0; t < 32; ++t) {
        const int kg = kbase + t * 64;
        // stage A: blend 5 streams, write split planes to global + smem
#pragma unroll
        for (int j = 0; j < 8; ++j) {
            const int row = arow + 16 * j;
            const size_t off = (size_t)(vbase + row) * VN + kg + ac4;
            float4 a = *(const float4*)(adjf + off);
            float4 b = *(const float4*)(pf1 + off);
            float4 c = *(const float4*)(adjs + off);
            float4 d = *(const float4*)(ps1 + off);
            float4 m = *(const float4*)(adjm + off);
            float4 r;
            r.x = fmaf(w0, a.x, fmaf(w1, b.x, fmaf(w2, c.x, fmaf(w3, d.x, m.x))));
            r.y = fmaf(w0, a.y, fmaf(w1, b.y, fmaf(w2, c.y, fmaf(w3, d.y, m.y))));
            r.z = fmaf(w0, a.z, fmaf(w1, b.z, fmaf(w2, c.z, fmaf(w3, d.z, m.z))));
            r.w = fmaf(w0, a.w, fmaf(w1, b.w, fmaf(w2, c.w, fmaf(w3, d.w, m.w))));
            rsp[j] += (r.x + r.y) + (r.z + r.w);
            uint32_t h0, l0, h1, l1;
            bsplit(r.x, r.y, h0, l0);
            bsplit(r.z, r.w, h1, l1);
            *reinterpret_cast<uint2*>(g_adjh + off) = make_uint2(h0, h1);
            *reinterpret_cast<uint2*>(g_adjl + off) = make_uint2(l0, l1);
            const int bo = (row * KA + ac4) * 2;
            *(uint2*)(smem + AHI_OFF + bo) = make_uint2(h0, h1);
            *(uint2*)(smem + ALO_OFF + bo) = make_uint2(l0, l1);
        }
        // stage B from data (fp32 -> split)
#pragma unroll
        for (int j = 0; j < 4; ++j) {
            const int id = tid + 256 * j;
            const int n = id >> 4, c4 = (id & 15) << 2;
            float4 v = *(const float4*)(data + (size_t)n * 16384 + kg + c4);
            uint32_t h0, l0, h1, l1;
            bsplit(v.x, v.y, h0, l0);
            bsplit(v.z, v.w, h1, l1);
            const int bo = (n * KA + c4) * 2;
            *(uint2*)(smem + BHI_OFF + bo) = make_uint2(h0, h1);
            *(uint2*)(smem + BLO_OFF + bo) = make_uint2(l0, l1);
        }
        __syncthreads();
        mma_tile(base, acc, aoff, boff);
        __syncthreads();
    }

    write_partials(acc, s, vbase, wid, lane);
#pragma unroll
    for (int j = 0; j < 8; ++j) {
        float v = rsp[j];
        v += __shfl_xor_sync(0xffffffffu, v, 1);
        v += __shfl_xor_sync(0xffffffffu, v, 2);
        v += __shfl_xor_sync(0xffffffffu, v, 4);
        v += __shfl_xor_sync(0xffffffffu, v, 8);
        if ((tid & 15) == 0) g_rspart[s][vbase + arow + 16 * j] = v;
    }
}

// ---------------- hops 2/3 GEMM: pure cp.async pipeline -----------------------
// grid (64, 2): KSPAN=4096, 64 tiles, double-buffered.
__global__ __launch_bounds__(256, 1) void k_gemm()
{
    extern __shared__ __align__(16) char smem[];
    const uint32_t base = smem_u32(smem);
    const int tid = threadIdx.x, lane = tid & 31, wid = tid >> 5;
    const int vbase = blockIdx.x * 128;
    const int kbase = blockIdx.y * 4096;

    uint32_t aoff, boff[4];
    frag_offsets(lane, wid, aoff, boff);

    float acc[8][4];
#pragma unroll
    for (int i = 0; i < 8; ++i)
#pragma unroll
        for (int j = 0; j < 4; ++j) acc[i][j] = 0.f;

    auto issue = [&](int t) {
        const uint32_t dst = base + (uint32_t)(t & 1) * BUFSZ;
        const int kg = kbase + t * 64;
#pragma unroll
        for (int j = 0; j < 4; ++j) {
            const int id = tid + 256 * j;
            const int row = id >> 3, ch = id & 7;
            const size_t go = (size_t)(vbase + row) * VN + kg + ch * 8;
            const uint32_t so = (uint32_t)(row * KA + ch * 8) * 2;
            cpa16(dst + AHI_OFF + so, g_adjh + go);
            cpa16(dst + ALO_OFF + so, g_adjl + go);
        }
#pragma unroll
        for (int j = 0; j < 2; ++j) {
            const int id = tid + 256 * j;
            const int n = id >> 3, ch = id & 7;
            const size_t go = (size_t)n * VN + kg + ch * 8;
            const uint32_t so = (uint32_t)(n * KA + ch * 8) * 2;
            cpa16(dst + BHI_OFF + so, g_XTh + go);
            cpa16(dst + BLO_OFF + so, g_XTl + go);
        }
        CP_COMMIT();
    };

    issue(0);
    issue(1);
    for (int t = 0; t < 64; ++t) {
        if (t < 63) asm volatile("cp.async.wait_group 1;" ::: "memory");
        else        asm volatile("cp.async.wait_group 0;" ::: "memory");
        __syncthreads();
        mma_tile(base + (uint32_t)(t & 1) * BUFSZ, acc, aoff, boff);
        __syncthreads();
        if (t + 2 < 64) issue(t + 2);
    }

    write_partials(acc, blockIdx.y, vbase, wid, lane);
}

// ---------------- combine kernels ---------------------------------------------
__device__ __forceinline__ void combine_body(int vbase, int tid, int nparts, int useRspart) {
    __shared__ float sm[64][65];
    __shared__ float rs[64];
    if (tid < 64) {
        float rv;
        if (useRspart) {
            rv = g_rspart[0][vbase + tid] + g_rspart[1][vbase + tid]
               + g_rspart[2][vbase + tid] + g_rspart[3][vbase + tid];
            g_rowsum[vbase + tid] = rv;
        } else {
            rv = g_rowsum[vbase + tid];
        }
        rs[tid] = rv;
    }
    __syncthreads();
#pragma unroll
    for (int j = 0; j < 4; ++j) {
        const int f = tid + j * 256;
        const int r = f >> 4, c = (f & 15) << 2;
        const size_t o = (size_t)(vbase + r) * NCOL + c;
        float4 p = *(const float4*)(g_part[0] + o);
        float4 q = *(const float4*)(g_part[1] + o);
        float4 v;
        v.x = p.x + q.x; v.y = p.y + q.y; v.z = p.z + q.z; v.w = p.w + q.w;
        if (nparts == 4) {
            float4 u = *(const float4*)(g_part[2] + o);
            float4 w = *(const float4*)(g_part[3] + o);
            v.x += u.x + w.x; v.y += u.y + w.y; v.z += u.z + w.z; v.w += u.w + w.w;
        }
        const float inv = 1.f / rs[r];
        v.x *= inv; v.y *= inv; v.z *= inv; v.w *= inv;
        *(float4*)(g_X + o) = v;
        sm[r][c] = v.x; sm[r][c + 1] = v.y; sm[r][c + 2] = v.z; sm[r][c + 3] = v.w;
    }
    __syncthreads();
    const int col = tid >> 2;
    const int v0 = (tid & 3) << 4;
#pragma unroll
    for (int j = 0; j < 4; ++j) {
        const int v = v0 + j * 4;
        float4 x;
        x.x = sm[v][col]; x.y = sm[v + 1][col]; x.z = sm[v + 2][col]; x.w = sm[v + 3][col];
        uint32_t h0, l0, h1, l1;
        bsplit(x.x, x.y, h0, l0);
        bsplit(x.z, x.w, h1, l1);
        *reinterpret_cast<uint2*>(g_XTh + (size_t)col * VN + vbase + v) = make_uint2(h0, h1);
        *reinterpret_cast<uint2*>(g_XTl + (size_t)col * VN + vbase + v) = make_uint2(l0, l1);
    }
}

__global__ __launch_bounds__(256) void k_combine1() {
    combine_body(blockIdx.x * 64, threadIdx.x, 4, 1);
}
__global__ __launch_bounds__(256) void k_combine() {
    combine_body(blockIdx.x * 64, threadIdx.x, 2, 0);
}

// ---------------- BN stats ---------------------------------------------------
__global__ __launch_bounds__(128) void k_stats(const float* __restrict__ W,
                                               const float* __restrict__ bias) {
    __shared__ float xs[1024];
    const int tid = threadIdx.x;
    const float* __restrict__ Xsrc = g_X + (size_t)4096 * NCOL + (size_t)blockIdx.x * 1024;
#pragma unroll
    for (int j = 0; j < 2; ++j)
        *(float4*)&xs[tid * 8 + j * 4] = *(const float4*)(Xsrc + tid * 8 + j * 4);
    __syncthreads();
    float w[16];
#pragma unroll
    for (int c = 0; c < 16; ++c) w[c] = W[tid * 16 + c];
    const float bb = bias[tid];
    float s = 0.f, ss = 0.f;
    for (int q = 0; q < 64; ++q) {
        const float* xq = &xs[q * 16];
        float y = bb;
#pragma unroll
        for (int c = 0; c < 16; ++c) y = fmaf(w[c], xq[c], y);
        s += y;
        ss = fmaf(y, y, ss);
    }
    g_s1[blockIdx.x * 128 + tid] = s;
    g_s2[blockIdx.x * 128 + tid] = ss;
}

__global__ void k_stats2() {
    const int o = threadIdx.x;
    float s = 0.f, ss = 0.f;
    for (int b2 = 0; b2 < 256; ++b2) { s += g_s1[b2 * 128 + o]; ss += g_s2[b2 * 128 + o]; }
    const float inv = 1.f / 16384.f;
    float mu = s * inv;
    float var = ss * inv - mu * mu;
    g_mu[o] = mu;
    g_rstd[o] = rsqrtf(var + 1e-5f);
}

// ---------------- GLU + BN apply + running max -------------------------------
__global__ __launch_bounds__(128) void k_glu(const float* __restrict__ W,
    const float* __restrict__ bias, const float* __restrict__ gamma,
    const float* __restrict__ beta, float* __restrict__ out, int first)
{
    __shared__ float Wsm[2048], bsm[128], gsm[128], besm[128], musm[128], rsm[128];
    const int tid = threadIdx.x;
    const int n = blockIdx.x * 128 + tid;
    const int b = blockIdx.y;
#pragma unroll
    for (int j = 0; j < 16; ++j) Wsm[tid * 16 + j] = W[tid * 16 + j];
    bsm[tid] = bias[tid]; gsm[tid] = gamma[tid]; besm[tid] = beta[tid];
    musm[tid] = g_mu[tid]; rsm[tid] = g_rstd[tid];
    __syncthreads();

    float xr[16];
    const float* __restrict__ xp = g_X + (size_t)4096 * NCOL + (size_t)n * 64 + b * 16;
#pragma unroll
    for (int j = 0; j < 4; ++j) {
        float4 t = *(const float4*)(xp + j * 4);
        xr[j * 4] = t.x; xr[j * 4 + 1] = t.y; xr[j * 4 + 2] = t.z; xr[j * 4 + 3] = t.w;
    }
    float* op = out + (size_t)b * (64 * 4096) + n;
    for (int f = 0; f < 64; ++f) {
        const float* wl = &Wsm[f * 16];
        const float* wr = &Wsm[(f + 64) * 16];
        float yl = bsm[f], yr = bsm[f + 64];
#pragma unroll
        for (int c = 0; c < 16; ++c) {
            yl = fmaf(wl[c], xr[c], yl);
            yr = fmaf(wr[c], xr[c], yr);
        }
        yl = fmaf(gsm[f] * (yl - musm[f]), rsm[f], besm[f]);
        yr = fmaf(gsm[f + 64] * (yr - musm[f + 64]), rsm[f + 64], besm[f + 64]);
        float val = yl / (1.f + expf(-yr));
        float* po = op + (size_t)f * 4096;
        if (first) *po = val;
        else       *po = fmaxf(*po, val);
    }
}

// ---------------- launch -----------------------------------------------------
extern "C" void kernel_launch(void* const* d_in, const int* in_sizes, int n_in,
                              void* d_out, int out_size)
{
    (void)in_sizes; (void)n_in; (void)out_size;
    const float* adjf = (const float*)d_in[0];
    const float* adjs = (const float*)d_in[1];
    const float* adjm = (const float*)d_in[2];
    const float* data = (const float*)d_in[3];
    const float* alf  = (const float*)d_in[4];
    const float* als  = (const float*)d_in[5];
    const float* gw   = (const float*)d_in[6];
    const float* gb   = (const float*)d_in[7];
    const float* gg   = (const float*)d_in[8];
    const float* gbe  = (const float*)d_in[9];
    float* out = (float*)d_out;

    cudaFuncSetAttribute(k_hop1, cudaFuncAttributeMaxDynamicSharedMemorySize, DSMEM_H1);
    cudaFuncSetAttribute(k_gemm, cudaFuncAttributeMaxDynamicSharedMemorySize, DSMEM_GEMM);

    k_alpha<<<1, 1>>>(alf, als);
    k_hop1<<<dim3(64, 4), 256, DSMEM_H1>>>(adjf, adjs, adjm, data);
    k_combine1<<<128, 256>>>();

    for (int h = 0; h < 3; ++h) {
        k_stats<<<256, 128>>>(gw + h * 2048, gb + h * 128);
        k_stats2<<<1, 128>>>();
        k_glu<<<dim3(32, 4), 128>>>(gw + h * 2048, gb + h * 128,
                                    gg + h * 128, gbe + h * 128, out, h == 0 ? 1 : 0);
        if (h < 2) {
            k_gemm<<<dim3(64, 2), 256, DSMEM_GEMM>>>();
            k_combine<<<128, 256>>>();
        }
    }
}

// round 8
// speedup vs baseline: 1.0573x; 1.0573x over previous
#include <cuda_runtime.h>
#include <cuda_bf16.h>
#include <math.h>
#include <stdint.h>

#define VN    8192
#define NCOL  64
#define KA    72            // smem row stride in bf16 (144B, LDSM conflict-free)

// smem plane byte offsets within one buffer
#define AHI_OFF 0
#define ALO_OFF 18432       // 128*72*2
#define BHI_OFF 36864
#define BLO_OFF 46080       // +64*72*2
#define BUFSZ   55296
#define STAGES  3
#define DSMEM_GEMM (STAGES*BUFSZ)   // 165888

// ---------------- device scratch ---------------------------------------------
__device__ __nv_bfloat16 g_adjh[(size_t)VN * VN];   // blended adj, bf16 hi
__device__ __nv_bfloat16 g_adjl[(size_t)VN * VN];   // bf16 lo residual
__device__ float g_rowsum[VN];
__device__ float g_part[2][(size_t)VN * NCOL];
__device__ float g_X[(size_t)VN * NCOL];            // hop output [v][col]
__device__ __nv_bfloat16 g_XTh[(size_t)NCOL * VN];  // B operand, split, [col][w]
__device__ __nv_bfloat16 g_XTl[(size_t)NCOL * VN];
__device__ float g_w4[4];
__device__ float g_s1[256 * 128];
__device__ float g_s2[256 * 128];
__device__ float g_mu[128];
__device__ float g_rstd[128];

// ---------------- helpers ------------------------------------------------------
__device__ __forceinline__ uint32_t smem_u32(const void* p) {
    uint32_t a;
    asm("{ .reg .u64 t; cvta.to.shared.u64 t, %1; cvt.u32.u64 %0, t; }" : "=r"(a) : "l"(p));
    return a;
}
__device__ __forceinline__ void bsplit(float x, float y, uint32_t& hi, uint32_t& lo) {
    __nv_bfloat162 h = __floats2bfloat162_rn(x, y);
    float hx = __bfloat162float(h.x), hy = __bfloat162float(h.y);
    __nv_bfloat162 l = __floats2bfloat162_rn(x - hx, y - hy);
    hi = *reinterpret_cast<uint32_t*>(&h);
    lo = *reinterpret_cast<uint32_t*>(&l);
}
__device__ __forceinline__ void mma_bf16(float* c,
    uint32_t a0, uint32_t a1, uint32_t a2, uint32_t a3, uint32_t b0, uint32_t b1) {
    asm volatile(
        "mma.sync.aligned.m16n8k16.row.col.f32.bf16.bf16.f32 "
        "{%0,%1,%2,%3}, {%4,%5,%6,%7}, {%8,%9}, {%0,%1,%2,%3};"
        : "+f"(c[0]), "+f"(c[1]), "+f"(c[2]), "+f"(c[3])
        : "r"(a0), "r"(a1), "r"(a2), "r"(a3), "r"(b0), "r"(b1));
}
__device__ __forceinline__ void ldsm4(uint32_t addr, uint32_t* r) {
    asm volatile("ldmatrix.sync.aligned.m8n8.x4.shared.b16 {%0,%1,%2,%3}, [%4];"
        : "=r"(r[0]), "=r"(r[1]), "=r"(r[2]), "=r"(r[3]) : "r"(addr));
}
__device__ __forceinline__ void cpa16(uint32_t dst, const void* src) {
    asm volatile("cp.async.cg.shared.global [%0], [%1], 16;" :: "r"(dst), "l"(src) : "memory");
}
#define CP_COMMIT() asm volatile("cp.async.commit_group;" ::: "memory")

// one 128x64x64 k-tile, 3-term bf16 split
__device__ __forceinline__ void mma_tile(uint32_t base, float acc[8][4],
                                         uint32_t aoff, const uint32_t* boff) {
#pragma unroll
    for (int ks = 0; ks < 4; ++ks) {
        const uint32_t kb = ks * 32;
        uint32_t ah[4], al[4];
        ldsm4(base + AHI_OFF + aoff + kb, ah);
        ldsm4(base + ALO_OFF + aoff + kb, al);
#pragma unroll
        for (int g = 0; g < 4; ++g) {
            uint32_t bh[4], bl[4];
            ldsm4(base + BHI_OFF + boff[g] + kb, bh);
            ldsm4(base + BLO_OFF + boff[g] + kb, bl);
            mma_bf16(acc[2*g],   ah[0],ah[1],ah[2],ah[3], bh[0],bh[1]);
            mma_bf16(acc[2*g],   ah[0],ah[1],ah[2],ah[3], bl[0],bl[1]);
            mma_bf16(acc[2*g],   al[0],al[1],al[2],al[3], bh[0],bh[1]);
            mma_bf16(acc[2*g+1], ah[0],ah[1],ah[2],ah[3], bh[2],bh[3]);
            mma_bf16(acc[2*g+1], ah[0],ah[1],ah[2],ah[3], bl[2],bl[3]);
            mma_bf16(acc[2*g+1], al[0],al[1],al[2],al[3], bh[2],bh[3]);
        }
    }
}

__device__ __forceinline__ void frag_offsets(int lane, int wid, uint32_t& aoff, uint32_t* boff) {
    const int rr = lane & 7, sel = lane >> 3;
    aoff = ((wid * 16 + (sel & 1) * 8 + rr) * KA + (sel >> 1) * 8) * 2;
#pragma unroll
    for (int g = 0; g < 4; ++g)
        boff[g] = ((g * 16 + (sel >> 1) * 8 + rr) * KA + (sel & 1) * 8) * 2;
}

__device__ __forceinline__ void write_partials(float acc[8][4], int s, int vbase,
                                               int wid, int lane) {
    float* dst = g_part[s] + (size_t)(vbase + wid * 16) * NCOL;
    const int gr = lane >> 2, cq = (lane & 3) * 2;
#pragma unroll
    for (int nb = 0; nb < 8; ++nb) {
        const int col = nb * 8 + cq;
        *(float2*)(dst + (size_t)gr * NCOL + col)       = make_float2(acc[nb][0], acc[nb][1]);
        *(float2*)(dst + (size_t)(gr + 8) * NCOL + col) = make_float2(acc[nb][2], acc[nb][3]);
    }
}

// ---------------- alpha softmax ----------------------------------------------
__global__ void k_alpha(const float* __restrict__ af, const float* __restrict__ as) {
    float e0 = expf(af[0]), e1 = expf(af[1]);
    g_w4[0] = e0 / (e0 + e1); g_w4[1] = e1 / (e0 + e1);
    float f0 = expf(as[0]), f1 = expf(as[1]);
    g_w4[2] = f0 / (f0 + f1); g_w4[3] = f1 / (f0 + f1);
}

// ---------------- prep: data -> split transposed B ([col][w]) -----------------
__global__ __launch_bounds__(256) void k_prepB(const float* __restrict__ data) {
    int fidx = blockIdx.x * 256 + threadIdx.x;   // 131072 float4s
    int col = fidx >> 11;
    int w4  = (fidx & 2047) << 2;
    float4 v = *(const float4*)(data + (size_t)col * 16384 + w4);
    uint32_t h0, l0, h1, l1;
    bsplit(v.x, v.y, h0, l0);
    bsplit(v.z, v.w, h1, l1);
    *reinterpret_cast<uint2*>(g_XTh + (size_t)col * VN + w4) = make_uint2(h0, h1);
    *reinterpret_cast<uint2*>(g_XTl + (size_t)col * VN + w4) = make_uint2(l0, l1);
}

// ---------------- blend: 5-stream -> split bf16 planes + rowsum ---------------
__global__ __launch_bounds__(256) void k_blend(
    const float* __restrict__ adjf, const float* __restrict__ adjs,
    const float* __restrict__ adjm)
{
    const int wid = threadIdx.x >> 5, lane = threadIdx.x & 31;
    const int row = blockIdx.x * 8 + wid;
    const size_t base = (size_t)row * VN;
    const float w0 = g_w4[0], w1 = g_w4[1], w2 = g_w4[2], w3 = g_w4[3];
    const float* __restrict__ a0 = adjf + base;
    const float* __restrict__ a1 = adjf + (size_t)VN * VN + base;
    const float* __restrict__ b0 = adjs + base;
    const float* __restrict__ b1 = adjs + (size_t)VN * VN + base;
    const float* __restrict__ m0 = adjm + base;
    __nv_bfloat16* __restrict__ dh = g_adjh + base;
    __nv_bfloat16* __restrict__ dl = g_adjl + base;
    float rs = 0.f;
    for (int i = lane; i < 2048; i += 64) {
#pragma unroll
        for (int u = 0; u < 2; ++u) {
            const int i4 = i + u * 32;
            const int o4 = i4 * 4;
            float4 a = *(const float4*)(a0 + o4);
            float4 b = *(const float4*)(a1 + o4);
            float4 c = *(const float4*)(b0 + o4);
            float4 d = *(const float4*)(b1 + o4);
            float4 m = *(const float4*)(m0 + o4);
            float4 r;
            r.x = fmaf(w0, a.x, fmaf(w1, b.x, fmaf(w2, c.x, fmaf(w3, d.x, m.x))));
            r.y = fmaf(w0, a.y, fmaf(w1, b.y, fmaf(w2, c.y, fmaf(w3, d.y, m.y))));
            r.z = fmaf(w0, a.z, fmaf(w1, b.z, fmaf(w2, c.z, fmaf(w3, d.z, m.z))));
            r.w = fmaf(w0, a.w, fmaf(w1, b.w, fmaf(w2, c.w, fmaf(w3, d.w, m.w))));
            rs += (r.x + r.y) + (r.z + r.w);
            uint32_t h0, l0, h1, l1;
            bsplit(r.x, r.y, h0, l0);
            bsplit(r.z, r.w, h1, l1);
            *reinterpret_cast<uint2*>(dh + o4) = make_uint2(h0, h1);
            *reinterpret_cast<uint2*>(dl + o4) = make_uint2(l0, l1);
        }
    }
    rs += __shfl_xor_sync(0xffffffffu, rs, 16);
    rs += __shfl_xor_sync(0xffffffffu, rs, 8);
    rs += __shfl_xor_sync(0xffffffffu, rs, 4);
    rs += __shfl_xor_sync(0xffffffffu, rs, 2);
    rs += __shfl_xor_sync(0xffffffffu, rs, 1);
    if (lane == 0) g_rowsum[row] = rs;
}

// ---------------- hop GEMM: 3-stage cp.async pipeline -------------------------
// grid (64, 2): 128-row M tiles x split-K. 64 k-tiles per CTA.
__global__ __launch_bounds__(256, 1) void k_gemm()
{
    extern __shared__ __align__(16) char smem[];
    const uint32_t base = smem_u32(smem);
    const int tid = threadIdx.x, lane = tid & 31, wid = tid >> 5;
    const int vbase = blockIdx.x * 128;
    const int kbase = blockIdx.y * 4096;

    uint32_t aoff, boff[4];
    frag_offsets(lane, wid, aoff, boff);

    float acc[8][4];
#pragma unroll
    for (int i = 0; i < 8; ++i)
#pragma unroll
        for (int j = 0; j < 4; ++j) acc[i][j] = 0.f;

    auto issue = [&](int t) {
        const uint32_t dst = base + (uint32_t)(t % STAGES) * BUFSZ;
        const int kg = kbase + t * 64;
#pragma unroll
        for (int j = 0; j < 4; ++j) {
            const int id = tid + 256 * j;
            const int row = id >> 3, ch = id & 7;
            const size_t go = (size_t)(vbase + row) * VN + kg + ch * 8;
            const uint32_t so = (uint32_t)(row * KA + ch * 8) * 2;
            cpa16(dst + AHI_OFF + so, g_adjh + go);
            cpa16(dst + ALO_OFF + so, g_adjl + go);
        }
#pragma unroll
        for (int j = 0; j < 2; ++j) {
            const int id = tid + 256 * j;
            const int n = id >> 3, ch = id & 7;
            const size_t go = (size_t)n * VN + kg + ch * 8;
            const uint32_t so = (uint32_t)(n * KA + ch * 8) * 2;
            cpa16(dst + BHI_OFF + so, g_XTh + go);
            cpa16(dst + BLO_OFF + so, g_XTl + go);
        }
        CP_COMMIT();
    };

    issue(0); issue(1); issue(2);
    for (int t = 0; t < 64; ++t) {
        if (t <= 61)      asm volatile("cp.async.wait_group 2;" ::: "memory");
        else if (t == 62) asm volatile("cp.async.wait_group 1;" ::: "memory");
        else              asm volatile("cp.async.wait_group 0;" ::: "memory");
        __syncthreads();
        mma_tile(base + (uint32_t)(t % STAGES) * BUFSZ, acc, aoff, boff);
        __syncthreads();
        if (t + STAGES < 64) issue(t + STAGES);
    }

    write_partials(acc, blockIdx.y, vbase, wid, lane);
}

// ---------------- combine: partials -> g_X and split transposed B -------------
__global__ __launch_bounds__(256) void k_combine() {
    __shared__ float sm[64][65];
    __shared__ float rs[64];
    const int tid = threadIdx.x;
    const int vbase = blockIdx.x * 64;
    if (tid < 64) rs[tid] = g_rowsum[vbase + tid];
    __syncthreads();
#pragma unroll
    for (int j = 0; j < 4; ++j) {
        const int f = tid + j * 256;
        const int r = f >> 4, c = (f & 15) << 2;
        const size_t o = (size_t)(vbase + r) * NCOL + c;
        float4 p = *(const float4*)(g_part[0] + o);
        float4 q = *(const float4*)(g_part[1] + o);
        const float inv = 1.f / rs[r];
        float4 v;
        v.x = (p.x + q.x) * inv; v.y = (p.y + q.y) * inv;
        v.z = (p.z + q.z) * inv; v.w = (p.w + q.w) * inv;
        *(float4*)(g_X + o) = v;
        sm[r][c] = v.x; sm[r][c + 1] = v.y; sm[r][c + 2] = v.z; sm[r][c + 3] = v.w;
    }
    __syncthreads();
    const int col = tid >> 2;
    const int v0 = (tid & 3) << 4;
#pragma unroll
    for (int j = 0; j < 4; ++j) {
        const int v = v0 + j * 4;
        float4 x;
        x.x = sm[v][col]; x.y = sm[v + 1][col]; x.z = sm[v + 2][col]; x.w = sm[v + 3][col];
        uint32_t h0, l0, h1, l1;
        bsplit(x.x, x.y, h0, l0);
        bsplit(x.z, x.w, h1, l1);
        *reinterpret_cast<uint2*>(g_XTh + (size_t)col * VN + vbase + v) = make_uint2(h0, h1);
        *reinterpret_cast<uint2*>(g_XTl + (size_t)col * VN + vbase + v) = make_uint2(l0, l1);
    }
}

// ---------------- BN stats ---------------------------------------------------
__global__ __launch_bounds__(128) void k_stats(const float* __restrict__ W,
                                               const float* __restrict__ bias) {
    __shared__ float xs[1024];
    const int tid = threadIdx.x;
    const float* __restrict__ Xsrc = g_X + (size_t)4096 * NCOL + (size_t)blockIdx.x * 1024;
#pragma unroll
    for (int j = 0; j < 2; ++j)
        *(float4*)&xs[tid * 8 + j * 4] = *(const float4*)(Xsrc + tid * 8 + j * 4);
    __syncthreads();
    float w[16];
#pragma unroll
    for (int c = 0; c < 16; ++c) w[c] = W[tid * 16 + c];
    const float bb = bias[tid];
    float s = 0.f, ss = 0.f;
    for (int q = 0; q < 64; ++q) {
        const float* xq = &xs[q * 16];
        float y = bb;
#pragma unroll
        for (int c = 0; c < 16; ++c) y = fmaf(w[c], xq[c], y);
        s += y;
        ss = fmaf(y, y, ss);
    }
    g_s1[blockIdx.x * 128 + tid] = s;
    g_s2[blockIdx.x * 128 + tid] = ss;
}

__global__ void k_stats2() {
    const int o = threadIdx.x;
    float s = 0.f, ss = 0.f;
    for (int b2 = 0; b2 < 256; ++b2) { s += g_s1[b2 * 128 + o]; ss += g_s2[b2 * 128 + o]; }
    const float inv = 1.f / 16384.f;
    float mu = s * inv;
    float var = ss * inv - mu * mu;
    g_mu[o] = mu;
    g_rstd[o] = rsqrtf(var + 1e-5f);
}

// ---------------- GLU + BN apply + running max -------------------------------
__global__ __launch_bounds__(128) void k_glu(const float* __restrict__ W,
    const float* __restrict__ bias, const float* __restrict__ gamma,
    const float* __restrict__ beta, float* __restrict__ out, int first)
{
    __shared__ float Wsm[2048], bsm[128], gsm[128], besm[128], musm[128], rsm[128];
    const int tid = threadIdx.x;
    const int n = blockIdx.x * 128 + tid;
    const int b = blockIdx.y;
#pragma unroll
    for (int j = 0; j < 16; ++j) Wsm[tid * 16 + j] = W[tid * 16 + j];
    bsm[tid] = bias[tid]; gsm[tid] = gamma[tid]; besm[tid] = beta[tid];
    musm[tid] = g_mu[tid]; rsm[tid] = g_rstd[tid];
    __syncthreads();

    float xr[16];
    const float* __restrict__ xp = g_X + (size_t)4096 * NCOL + (size_t)n * 64 + b * 16;
#pragma unroll
    for (int j = 0; j < 4; ++j) {
        float4 t = *(const float4*)(xp + j * 4);
        xr[j * 4] = t.x; xr[j * 4 + 1] = t.y; xr[j * 4 + 2] = t.z; xr[j * 4 + 3] = t.w;
    }
    float* op = out + (size_t)b * (64 * 4096) + n;
    for (int f = 0; f < 64; ++f) {
        const float* wl = &Wsm[f * 16];
        const float* wr = &Wsm[(f + 64) * 16];
        float yl = bsm[f], yr = bsm[f + 64];
#pragma unroll
        for (int c = 0; c < 16; ++c) {
            yl = fmaf(wl[c], xr[c], yl);
            yr = fmaf(wr[c], xr[c], yr);
        }
        yl = fmaf(gsm[f] * (yl - musm[f]), rsm[f], besm[f]);
        yr = fmaf(gsm[f + 64] * (yr - musm[f + 64]), rsm[f + 64], besm[f + 64]);
        float val = yl / (1.f + expf(-yr));
        float* po = op + (size_t)f * 4096;
        if (first) *po = val;
        else       *po = fmaxf(*po, val);
    }
}

// ---------------- launch -----------------------------------------------------
extern "C" void kernel_launch(void* const* d_in, const int* in_sizes, int n_in,
                              void* d_out, int out_size)
{
    (void)in_sizes; (void)n_in; (void)out_size;
    const float* adjf = (const float*)d_in[0];
    const float* adjs = (const float*)d_in[1];
    const float* adjm = (const float*)d_in[2];
    const float* data = (const float*)d_in[3];
    const float* alf  = (const float*)d_in[4];
    const float* als  = (const float*)d_in[5];
    const float* gw   = (const float*)d_in[6];
    const float* gb   = (const float*)d_in[7];
    const float* gg   = (const float*)d_in[8];
    const float* gbe  = (const float*)d_in[9];
    float* out = (float*)d_out;

    cudaFuncSetAttribute(k_gemm, cudaFuncAttributeMaxDynamicSharedMemorySize, DSMEM_GEMM);

    k_alpha<<<1, 1>>>(alf, als);
    k_prepB<<<512, 256>>>(data);
    k_blend<<<1024, 256>>>(adjf, adjs, adjm);

    for (int h = 0; h < 3; ++h) {
        k_gemm<<<dim3(64, 2), 256, DSMEM_GEMM>>>();
        k_combine<<<128, 256>>>();
        k_stats<<<256, 128>>>(gw + h * 2048, gb + h * 128);
        k_stats2<<<1, 128>>>();
        k_glu<<<dim3(32, 4), 128>>>(gw + h * 2048, gb + h * 128,
                                    gg + h * 128, gbe + h * 128, out, h == 0 ? 1 : 0);
    }
}